// round 6
// baseline (speedup 1.0000x reference)
#include <cuda_runtime.h>
#include <math.h>

typedef unsigned long long ull;

#define BB 16
#define NN 500
#define TT 128
#define NP 512
#define XGC 336
#define KT 16

__device__ float g_H   [BB*64 *NP];
__device__ float g_XG5 [BB*XGC*NP];
__device__ float g_CG5 [BB*XGC*NP];
__device__ float g_XIN [BB*64 *NP];
__device__ float g_XIN2[BB*128*NP];
__device__ float g_OUT [BB*64 *NP];
__device__ float g_U   [BB*64 *NP];
__device__ float g_Wc2 [64*192];
__device__ float g_bc2 [64];

__device__ unsigned g_cnt;
__device__ volatile unsigned g_gen;

__device__ __forceinline__ ull pack2(float x, float y) {
    ull r; asm("mov.b64 %0, {%1,%2};" : "=l"(r) : "f"(x), "f"(y)); return r;
}
__device__ __forceinline__ void unpack2(ull p, float& x, float& y) {
    asm("mov.b64 {%0,%1}, %2;" : "=f"(x), "=f"(y) : "l"(p));
}
__device__ __forceinline__ void fma2(ull& d, ull a, ull b) {
    asm("fma.rn.f32x2 %0, %1, %2, %0;" : "+l"(d) : "l"(a), "l"(b));
}

__device__ __forceinline__ void gridbar() {
    __syncthreads();
    if (threadIdx.x == 0) {
        unsigned gen = g_gen;
        __threadfence();
        if (atomicAdd(&g_cnt, 1u) == gridDim.x - 1u) {
            atomicExch(&g_cnt, 0u);
            __threadfence();
            g_gen = gen + 1u;
        } else {
            while (g_gen == gen) __nanosleep(64);
        }
        __threadfence();
    }
    __syncthreads();
}

// 64x64 tile, 128 threads: tx=tid&7 (8 n), ty=tid>>3 (4 m).
// Ad: ull[KT*64] (A duplicated pairs, [k][m]); Bd: float[KT*64] ([k][n]).
__device__ __forceinline__ void mmtile(const ull* __restrict__ Ad,
                                       const float* __restrict__ Bd,
                                       ull acc[4][4], int tx, int ty)
{
#pragma unroll
    for (int kk = 0; kk < KT; kk++) {
        const ull* ar = Ad + kk * 64 + ty * 4;
        ulonglong2 A0 = *(const ulonglong2*)(ar);
        ulonglong2 A1 = *(const ulonglong2*)(ar + 2);
        const ull* br = (const ull*)(Bd + kk * 64 + tx * 8);
        ulonglong2 B0 = *(const ulonglong2*)(br);
        ulonglong2 B1 = *(const ulonglong2*)(br + 2);
        fma2(acc[0][0], A0.x, B0.x); fma2(acc[0][1], A0.x, B0.y);
        fma2(acc[0][2], A0.x, B1.x); fma2(acc[0][3], A0.x, B1.y);
        fma2(acc[1][0], A0.y, B0.x); fma2(acc[1][1], A0.y, B0.y);
        fma2(acc[1][2], A0.y, B1.x); fma2(acc[1][3], A0.y, B1.y);
        fma2(acc[2][0], A1.x, B0.x); fma2(acc[2][1], A1.x, B0.y);
        fma2(acc[2][2], A1.x, B1.x); fma2(acc[2][3], A1.x, B1.y);
        fma2(acc[3][0], A1.y, B0.x); fma2(acc[3][1], A1.y, B0.y);
        fma2(acc[3][2], A1.y, B1.x); fma2(acc[3][3], A1.y, B1.y);
    }
}

// dst[b, dstOff+c, w] = sum_v src[b, srcOff+c, v] * A[w, v]
__device__ void diff_tile(const float* __restrict__ src, float* __restrict__ dst,
                          const float* __restrict__ A,
                          int C, int srcOff, int dstOff, size_t srcBS, size_t dstBS,
                          int m0, int n0, ull* sAp, float* sB)
{
    const int tid = threadIdx.x;
    const int r = tid & 63, kb0 = (tid >> 6) * 8;
    const int tx = tid & 7, ty = tid >> 3;
    const int M = C * BB;

    const float* srow = 0;
    { int gm = m0 + r;
      if (gm < M) { int b = gm / C, c = gm - b * C;
          srow = src + (size_t)b * srcBS + (size_t)(srcOff + c) * NP; } }
    const float* arow = 0;
    { int gn = n0 + r; if (gn < NN) arow = A + (size_t)gn * NN; }

    ull acc[4][4] = {};
    const float4 Z = make_float4(0.f, 0.f, 0.f, 0.f);
    float4 a0 = srow ? *(const float4*)(srow + kb0) : Z;
    float4 a1 = srow ? *(const float4*)(srow + kb0 + 4) : Z;
    float4 b0 = (arow && kb0     < NN) ? *(const float4*)(arow + kb0) : Z;
    float4 b1 = (arow && kb0 + 4 < NN) ? *(const float4*)(arow + kb0 + 4) : Z;

    int buf = 0;
    for (int kt = 0; kt < NP / KT; kt++) {
        ull* Ad = sAp + buf * (KT * 64);
        float* Bd = sB + buf * (KT * 64);
        Ad[(kb0+0)*64+r] = pack2(a0.x, a0.x); Ad[(kb0+1)*64+r] = pack2(a0.y, a0.y);
        Ad[(kb0+2)*64+r] = pack2(a0.z, a0.z); Ad[(kb0+3)*64+r] = pack2(a0.w, a0.w);
        Ad[(kb0+4)*64+r] = pack2(a1.x, a1.x); Ad[(kb0+5)*64+r] = pack2(a1.y, a1.y);
        Ad[(kb0+6)*64+r] = pack2(a1.z, a1.z); Ad[(kb0+7)*64+r] = pack2(a1.w, a1.w);
        Bd[(kb0+0)*64+r] = b0.x; Bd[(kb0+1)*64+r] = b0.y;
        Bd[(kb0+2)*64+r] = b0.z; Bd[(kb0+3)*64+r] = b0.w;
        Bd[(kb0+4)*64+r] = b1.x; Bd[(kb0+5)*64+r] = b1.y;
        Bd[(kb0+6)*64+r] = b1.z; Bd[(kb0+7)*64+r] = b1.w;
        __syncthreads();
        if (kt + 1 < NP / KT) {
            int kb = (kt + 1) * KT + kb0;
            a0 = srow ? *(const float4*)(srow + kb) : Z;
            a1 = srow ? *(const float4*)(srow + kb + 4) : Z;
            b0 = (arow && kb     < NN) ? *(const float4*)(arow + kb) : Z;
            b1 = (arow && kb + 4 < NN) ? *(const float4*)(arow + kb + 4) : Z;
        }
        mmtile(Ad, Bd, acc, tx, ty);
        buf ^= 1;
    }

#pragma unroll
    for (int i = 0; i < 4; i++) {
        int gm = m0 + ty * 4 + i;
        if (gm >= M) continue;
        int b = gm / C, c = gm - b * C;
        float* drow = dst + (size_t)b * dstBS + (size_t)(dstOff + c) * NP + n0 + tx * 8;
#pragma unroll
        for (int j = 0; j < 4; j++) {
            int gn = n0 + tx * 8 + 2 * j;
            if (gn < NN) {
                float v0, v1; unpack2(acc[i][j], v0, v1);
                *(float2*)(drow + 2 * j) = make_float2(v0, v1);
            }
        }
    }
    __syncthreads();
}

// out[b,o,n] = act(sum_k W[o,k]*X[b,k,n] + bias[o]), O=64, X=concat(S1,S2)
// mode 0: ->dst | 1: prelu->g_OUT + reps | 2: sigmoid->g_U
// mode 3: sigmoid*h->g_CG5[2+o] | 4: tanh, h=u*h+(1-u)*c
__device__ void conv_tile(const float* __restrict__ S1, int C1, size_t s1BS,
                          const float* __restrict__ S2, size_t s2BS,
                          const float* __restrict__ W, const float* __restrict__ bias,
                          int K, int b, int n0, int mode,
                          float* __restrict__ dst, float* __restrict__ reps,
                          int t, float pav, ull* sAp, float* sB)
{
    const int tid = threadIdx.x;
    const int o_l = tid & 63, kb0 = (tid >> 6) * 8;
    const int kx = tid >> 3, nc = (tid & 7) * 8;
    const int tx = tid & 7, ty = tid >> 3;
    const int nkt = (K + KT - 1) / KT;

    ull acc[4][4] = {};
    float rw[8]; float4 x0, x1v;
    {
#pragma unroll
        for (int s = 0; s < 8; s++) {
            int k = kb0 + s;
            rw[s] = (k < K) ? W[(size_t)o_l * K + k] : 0.f;
        }
        const float* row = (kx < C1) ? S1 + (size_t)b * s1BS + (size_t)kx * NP
                                     : S2 + (size_t)b * s2BS + (size_t)(kx - C1) * NP;
        x0  = *(const float4*)(row + n0 + nc);
        x1v = *(const float4*)(row + n0 + nc + 4);
    }

    int buf = 0;
    for (int kt = 0; kt < nkt; kt++) {
        ull* Ad = sAp + buf * (KT * 64);
        float* Bd = sB + buf * (KT * 64);
#pragma unroll
        for (int s = 0; s < 8; s++) Ad[(kb0 + s) * 64 + o_l] = pack2(rw[s], rw[s]);
        *(float4*)(Bd + kx * 64 + nc)     = x0;
        *(float4*)(Bd + kx * 64 + nc + 4) = x1v;
        __syncthreads();
        if (kt + 1 < nkt) {
            int kb = (kt + 1) * KT;
#pragma unroll
            for (int s = 0; s < 8; s++) {
                int k = kb + kb0 + s;
                rw[s] = (k < K) ? W[(size_t)o_l * K + k] : 0.f;
            }
            int kg = kb + kx;
            const float* row = (kg < C1) ? S1 + (size_t)b * s1BS + (size_t)kg * NP
                                         : S2 + (size_t)b * s2BS + (size_t)(kg - C1) * NP;
            x0  = *(const float4*)(row + n0 + nc);
            x1v = *(const float4*)(row + n0 + nc + 4);
        }
        mmtile(Ad, Bd, acc, tx, ty);
        buf ^= 1;
    }

#pragma unroll
    for (int i = 0; i < 4; i++) {
        int o = ty * 4 + i;
        float bs = bias[o];
        size_t rowIdx = ((size_t)b * 64 + o) * NP + n0 + tx * 8;
#pragma unroll
        for (int j = 0; j < 4; j++) {
            int gn = n0 + tx * 8 + 2 * j;
            if (gn >= NN) continue;
            float v0, v1; unpack2(acc[i][j], v0, v1);
            v0 += bs; v1 += bs;
            if (mode == 0) {
                *(float2*)(dst + rowIdx + 2 * j) = make_float2(v0, v1);
            } else if (mode == 1) {
                float o0 = v0 >= 0.f ? v0 : pav * v0;
                float o1 = v1 >= 0.f ? v1 : pav * v1;
                *(float2*)(g_OUT + rowIdx + 2 * j) = make_float2(o0, o1);
                size_t rb = (((size_t)b * 128 + o) * NN + gn) * TT + t;
                reps[rb] = o0; reps[rb + TT] = o1;
            } else if (mode == 2) {
                *(float2*)(g_U + rowIdx + 2 * j) =
                    make_float2(1.f / (1.f + expf(-v0)), 1.f / (1.f + expf(-v1)));
            } else if (mode == 3) {
                float2 h2 = *(const float2*)(g_H + rowIdx + 2 * j);
                *(float2*)(g_CG5 + ((size_t)b * XGC + 2 + o) * NP + n0 + tx * 8 + 2 * j) =
                    make_float2(h2.x / (1.f + expf(-v0)), h2.y / (1.f + expf(-v1)));
            } else {
                float c0 = tanhf(v0), c1 = tanhf(v1);
                float2 u2 = *(const float2*)(g_U + rowIdx + 2 * j);
                float2 h2 = *(const float2*)(g_H + rowIdx + 2 * j);
                *(float2*)(g_H + rowIdx + 2 * j) =
                    make_float2(u2.x * h2.x + (1.f - u2.x) * c0,
                                u2.y * h2.y + (1.f - u2.y) * c1);
            }
        }
    }
    __syncthreads();
}

__global__ void __launch_bounds__(128, 2) kmain(
    const float* __restrict__ x, const float* __restrict__ af,
    const float* __restrict__ ab, const int* __restrict__ mask,
    const float* __restrict__ Wr,  const float* __restrict__ br,
    const float* __restrict__ Wu,  const float* __restrict__ bu,
    const float* __restrict__ Wc,  const float* __restrict__ bc,
    const float* __restrict__ Wfs, const float* __restrict__ bfs,
    const float* __restrict__ Wli, const float* __restrict__ bli,
    const float* __restrict__ Wgc, const float* __restrict__ bgc,
    const float* __restrict__ Wlo, const float* __restrict__ blo,
    const float* __restrict__ Wro, const float* __restrict__ bro,
    const float* __restrict__ pa,
    float* __restrict__ imp, float* __restrict__ pred, float* __restrict__ reps)
{
    __shared__ __align__(16) ull   sAp[2 * KT * 64];
    __shared__ __align__(16) float sB [2 * KT * 64];

    const int tid = threadIdx.x;
    const int nb = gridDim.x;
    const int gtid = blockIdx.x * 128 + tid;
    const int gstr = nb * 128;
    const float pav = *pa;

    // prologue: zero H; fold W_gc into W_lo
    for (int i = gtid; i < BB * 64 * NP; i += gstr) g_H[i] = 0.f;
    for (int i = gtid; i < 64 * 192; i += gstr) {
        int o = i / 192, k = i - o * 192;
        float s;
        if (k < 128) {
            s = 0.f;
            for (int j = 0; j < 64; j++) s += Wlo[o * 128 + j] * Wgc[j * 128 + k];
        } else s = Wlo[o * 128 + 64 + (k - 128)];
        g_Wc2[i] = s;
    }
    for (int i = gtid; i < 64; i += gstr) {
        float s = blo[i];
        for (int j = 0; j < 64; j++) s += Wlo[i * 128 + j] * bgc[j];
        g_bc2[i] = s;
    }
    gridbar();

    for (int t = 0; t < TT; t++) {
        // stage A: pred, x1, mf; pack XG[0..65]; CG[1]=mf; reps h-half
        for (int i = gtid; i < BB * NN; i += gstr) {
            int b = i / NN, n = i - b * NN;
            const float* h = g_H + (size_t)b * 64 * NP + n;
            float* xg = g_XG5 + (size_t)b * XGC * NP + n;
            float* rb = reps + (((size_t)b * 128 + 64) * NN + n) * TT + t;
            float s = bfs[0];
#pragma unroll 8
            for (int c = 0; c < 64; c++) {
                float hv = h[(size_t)c * NP];
                s += Wfs[c] * hv;
                xg[(size_t)(2 + c) * NP] = hv;
                rb[(size_t)c * NN * TT] = hv;
            }
            size_t xi = ((size_t)b * NN + n) * TT + t;
            pred[xi] = s;
            int mk = mask[xi];
            xg[0]  = mk ? x[xi] : s;
            xg[NP] = (float)mk;
            g_CG5[(size_t)b * XGC * NP + NP + n] = (float)mk;
        }
        gridbar();

        // conv li: XG5[0..65] -> XIN
        for (int tile = blockIdx.x; tile < 128; tile += nb)
            conv_tile(g_XG5, 1000, (size_t)XGC * NP, g_XG5, 0, Wli, bli, 66,
                      tile >> 3, (tile & 7) * 64, 0, g_XIN, reps, t, pav, sAp, sB);
        gridbar();

        // diffusion XIN -> XIN2 (Df|Db)
        for (int tile = blockIdx.x; tile < 256; tile += nb) {
            int z = tile >> 7, rem = tile & 127;
            diff_tile(g_XIN, g_XIN2, z ? ab : af, 64, 0, z * 64,
                      (size_t)64 * NP, (size_t)128 * NP,
                      (rem >> 3) * 64, (rem & 7) * 64, sAp, sB);
        }
        gridbar();

        // combined gc∘lo conv: [XIN2(128), H(64)] K=192 -> OUT (prelu) + reps
        for (int tile = blockIdx.x; tile < 128; tile += nb)
            conv_tile(g_XIN2, 128, (size_t)128 * NP, g_H, (size_t)64 * NP,
                      g_Wc2, g_bc2, 192,
                      tile >> 3, (tile & 7) * 64, 1, g_OUT, reps, t, pav, sAp, sB);
        gridbar();

        // stage B: imp, x2 -> XG5[0], CG5[0]
        for (int i = gtid; i < BB * NN; i += gstr) {
            int b = i / NN, n = i - b * NN;
            const float* o = g_OUT + (size_t)b * 64 * NP + n;
            const float* h = g_H   + (size_t)b * 64 * NP + n;
            float s = bro[0];
#pragma unroll 8
            for (int c = 0; c < 64; c++)
                s += Wro[c] * o[(size_t)c * NP] + Wro[64 + c] * h[(size_t)c * NP];
            size_t xi = ((size_t)b * NN + n) * TT + t;
            imp[xi] = s;
            int mk = mask[xi];
            float* xg0 = g_XG5 + (size_t)b * XGC * NP + n;
            float x2 = mk ? *xg0 : s;
            *xg0 = x2;
            g_CG5[(size_t)b * XGC * NP + n] = x2;
        }
        gridbar();

        // diffusion XG order-2
        for (int tile = blockIdx.x; tile < 272; tile += nb) {
            int z = tile / 136, rem = tile - z * 136;
            diff_tile(g_XG5, g_XG5, z ? ab : af, 66, 0, 66 + z * 132,
                      (size_t)XGC * NP, (size_t)XGC * NP,
                      (rem >> 3) * 64, (rem & 7) * 64, sAp, sB);
        }
        gridbar();
        for (int tile = blockIdx.x; tile < 272; tile += nb) {
            int z = tile / 136, rem = tile - z * 136;
            diff_tile(g_XG5, g_XG5, z ? ab : af, 66, 66 + z * 132, 132 + z * 132,
                      (size_t)XGC * NP, (size_t)XGC * NP,
                      (rem >> 3) * 64, (rem & 7) * 64, sAp, sB);
        }
        gridbar();

        // convs r (-> r*h into CG5[2..65]) and u (-> U)
        for (int tile = blockIdx.x; tile < 256; tile += nb) {
            int tl = tile & 127;
            if (tile < 128)
                conv_tile(g_XG5, 1000, (size_t)XGC * NP, g_XG5, 0, Wr, br, 330,
                          tl >> 3, (tl & 7) * 64, 3, g_U, reps, t, pav, sAp, sB);
            else
                conv_tile(g_XG5, 1000, (size_t)XGC * NP, g_XG5, 0, Wu, bu, 330,
                          tl >> 3, (tl & 7) * 64, 2, g_U, reps, t, pav, sAp, sB);
        }
        gridbar();

        // diffusion CG order-2
        for (int tile = blockIdx.x; tile < 272; tile += nb) {
            int z = tile / 136, rem = tile - z * 136;
            diff_tile(g_CG5, g_CG5, z ? ab : af, 66, 0, 66 + z * 132,
                      (size_t)XGC * NP, (size_t)XGC * NP,
                      (rem >> 3) * 64, (rem & 7) * 64, sAp, sB);
        }
        gridbar();
        for (int tile = blockIdx.x; tile < 272; tile += nb) {
            int z = tile / 136, rem = tile - z * 136;
            diff_tile(g_CG5, g_CG5, z ? ab : af, 66, 66 + z * 132, 132 + z * 132,
                      (size_t)XGC * NP, (size_t)XGC * NP,
                      (rem >> 3) * 64, (rem & 7) * 64, sAp, sB);
        }
        gridbar();

        // conv c: tanh + h = u*h + (1-u)*c
        for (int tile = blockIdx.x; tile < 128; tile += nb)
            conv_tile(g_CG5, 1000, (size_t)XGC * NP, g_CG5, 0, Wc, bc, 330,
                      tile >> 3, (tile & 7) * 64, 4, g_U, reps, t, pav, sAp, sB);
        gridbar();
    }
}

extern "C" void kernel_launch(void* const* d_in, const int* in_sizes, int n_in,
                              void* d_out, int out_size)
{
    const float* x    = (const float*)d_in[0];
    const float* af   = (const float*)d_in[1];
    const float* ab   = (const float*)d_in[2];
    const int*   mask = (const int*)  d_in[3];
    const float* Wr   = (const float*)d_in[4];
    const float* br   = (const float*)d_in[5];
    const float* Wu   = (const float*)d_in[6];
    const float* bu   = (const float*)d_in[7];
    const float* Wc   = (const float*)d_in[8];
    const float* bc   = (const float*)d_in[9];
    const float* Wfs  = (const float*)d_in[10];
    const float* bfs  = (const float*)d_in[11];
    const float* Wli  = (const float*)d_in[12];
    const float* bli  = (const float*)d_in[13];
    const float* Wgc  = (const float*)d_in[14];
    const float* bgc  = (const float*)d_in[15];
    const float* Wlo  = (const float*)d_in[16];
    const float* blo  = (const float*)d_in[17];
    const float* Wro  = (const float*)d_in[18];
    const float* bro  = (const float*)d_in[19];
    const float* pa   = (const float*)d_in[20];

    float* out_imp  = (float*)d_out;
    float* out_pred = out_imp + (size_t)BB * NN * TT;
    float* out_reps = out_imp + (size_t)2 * BB * NN * TT;

    int dev = 0; cudaGetDevice(&dev);
    int sm = 0;
    cudaDeviceGetAttribute(&sm, cudaDevAttrMultiProcessorCount, dev);
    if (sm <= 0) sm = 148;
    int per = 0;
    cudaOccupancyMaxActiveBlocksPerMultiprocessor(&per, kmain, 128, 0);
    if (per < 1) per = 1;
    if (per > 2) per = 2;
    int nb = sm * per;

    kmain<<<nb, 128>>>(x, af, ab, mask, Wr, br, Wu, bu, Wc, bc,
                       Wfs, bfs, Wli, bli, Wgc, bgc, Wlo, blo, Wro, bro, pa,
                       out_imp, out_pred, out_reps);
}

// round 7
// speedup vs baseline: 1.1316x; 1.1316x over previous
#include <cuda_runtime.h>
#include <math.h>

typedef unsigned long long ull;

#define BB 16
#define NN 500
#define TT 128
#define NP 512
#define XGC 336
#define KT 16

__device__ float g_H   [BB*64 *NP];
__device__ float g_XG5 [BB*XGC*NP];
__device__ float g_CG5 [BB*XGC*NP];
__device__ float g_XIN [BB*64 *NP];
__device__ float g_XIN2[BB*128*NP];
__device__ float g_OUT [BB*64 *NP];
__device__ float g_U   [BB*64 *NP];
__device__ float g_Wc2 [64*192];
__device__ float g_bc2 [64];

__device__ unsigned g_cnt;
__device__ volatile unsigned g_gen;

__device__ __forceinline__ ull pack2(float x, float y) {
    ull r; asm("mov.b64 %0, {%1,%2};" : "=l"(r) : "f"(x), "f"(y)); return r;
}
__device__ __forceinline__ void unpack2(ull p, float& x, float& y) {
    asm("mov.b64 {%0,%1}, %2;" : "=f"(x), "=f"(y) : "l"(p));
}
__device__ __forceinline__ void fma2(ull& d, ull a, ull b) {
    asm("fma.rn.f32x2 %0, %1, %2, %0;" : "+l"(d) : "l"(a), "l"(b));
}

__device__ __forceinline__ void gridbar() {
    __syncthreads();
    if (threadIdx.x == 0) {
        unsigned gen = g_gen;
        __threadfence();
        if (atomicAdd(&g_cnt, 1u) == gridDim.x - 1u) {
            atomicExch(&g_cnt, 0u);
            __threadfence();
            g_gen = gen + 1u;
        } else {
            while (g_gen == gen) __nanosleep(64);
        }
        __threadfence();
    }
    __syncthreads();
}

// 64x64 tile, 256 threads: tx=tid&15 (4 n each), ty=tid>>4 (4 m each).
// Ad: ull[KT*64] A as duplicated f32x2 pairs [k][m]; Bd: float[KT*64] [k][n].
__device__ __forceinline__ void mmtile(const ull* __restrict__ Ad,
                                       const float* __restrict__ Bd,
                                       ull acc[4][2], int tx, int ty)
{
#pragma unroll
    for (int kk = 0; kk < KT; kk++) {
        const ull* ar = Ad + kk * 64 + ty * 4;
        ulonglong2 A0 = *(const ulonglong2*)(ar);
        ulonglong2 A1 = *(const ulonglong2*)(ar + 2);
        ulonglong2 B0 = *(const ulonglong2*)((const ull*)(Bd + kk * 64) + tx * 2);
        fma2(acc[0][0], A0.x, B0.x); fma2(acc[0][1], A0.x, B0.y);
        fma2(acc[1][0], A0.y, B0.x); fma2(acc[1][1], A0.y, B0.y);
        fma2(acc[2][0], A1.x, B0.x); fma2(acc[2][1], A1.x, B0.y);
        fma2(acc[3][0], A1.y, B0.x); fma2(acc[3][1], A1.y, B0.y);
    }
}

// dst[b, dstOff+c, w] = sum_v src[b, srcOff+c, v] * A[w, v]
// src node-padded to NP with zeros (never written past NN) => pad contributes 0.
__device__ void diff_tile(const float* __restrict__ src, float* __restrict__ dst,
                          const float* __restrict__ A,
                          int C, int srcOff, int dstOff, size_t srcBS, size_t dstBS,
                          int m0, int n0, ull* sAp, float* sB)
{
    const int tid = threadIdx.x;
    const int r = tid & 63, ks = tid >> 6;         // loader: row r, k-segment ks
    const int kb0 = ks * 4;
    const int tx = tid & 15, ty = tid >> 4;
    const int M = C * BB;

    const float* srow = 0;
    { int gm = m0 + r;
      if (gm < M) { int b = gm / C, c = gm - b * C;
          srow = src + (size_t)b * srcBS + (size_t)(srcOff + c) * NP; } }
    const float* arow = 0;
    { int gn = n0 + r; if (gn < NN) arow = A + (size_t)gn * NN; }

    ull acc[4][2] = {};
    const float4 Z = make_float4(0.f, 0.f, 0.f, 0.f);
    float4 va = srow ? *(const float4*)(srow + kb0) : Z;
    float4 vb = (arow && kb0 < NN) ? *(const float4*)(arow + kb0) : Z;

    int buf = 0;
    for (int kt = 0; kt < NP / KT; kt++) {
        ull* Ad = sAp + buf * (KT * 64);
        float* Bd = sB + buf * (KT * 64);
        Ad[(kb0+0)*64+r] = pack2(va.x, va.x); Ad[(kb0+1)*64+r] = pack2(va.y, va.y);
        Ad[(kb0+2)*64+r] = pack2(va.z, va.z); Ad[(kb0+3)*64+r] = pack2(va.w, va.w);
        Bd[(kb0+0)*64+r] = vb.x; Bd[(kb0+1)*64+r] = vb.y;
        Bd[(kb0+2)*64+r] = vb.z; Bd[(kb0+3)*64+r] = vb.w;
        __syncthreads();
        if (kt + 1 < NP / KT) {
            int kb = (kt + 1) * KT + kb0;
            va = srow ? *(const float4*)(srow + kb) : Z;
            vb = (arow && kb < NN) ? *(const float4*)(arow + kb) : Z;
        }
        mmtile(Ad, Bd, acc, tx, ty);
        buf ^= 1;
    }

#pragma unroll
    for (int i = 0; i < 4; i++) {
        int gm = m0 + ty * 4 + i;
        if (gm >= M) continue;
        int b = gm / C, c = gm - b * C;
        float* drow = dst + (size_t)b * dstBS + (size_t)(dstOff + c) * NP + n0 + tx * 4;
#pragma unroll
        for (int j = 0; j < 2; j++) {
            int gn = n0 + tx * 4 + 2 * j;
            if (gn < NN) {
                float v0, v1; unpack2(acc[i][j], v0, v1);
                *(float2*)(drow + 2 * j) = make_float2(v0, v1);
            }
        }
    }
    __syncthreads();
}

// out[b,o,n] = act(sum_k W[o,k]*X[b,k,n] + bias[o]), O=64, X=concat(S1,S2)
// mode 0: ->dst | 1: prelu->g_OUT + reps | 2: sigmoid->g_U
// mode 3: sigmoid*h->g_CG5[2+o] | 4: tanh, h=u*h+(1-u)*c
__device__ void conv_tile(const float* __restrict__ S1, int C1, size_t s1BS,
                          const float* __restrict__ S2, size_t s2BS,
                          const float* __restrict__ W, const float* __restrict__ bias,
                          int K, int b, int n0, int mode,
                          float* __restrict__ dst, float* __restrict__ reps,
                          int t, float pav, ull* sAp, float* sB)
{
    const int tid = threadIdx.x;
    const int o_l = tid & 63, ks = tid >> 6;
    const int kb0 = ks * 4;
    const int kx = tid >> 4, nc = (tid & 15) * 4;
    const int tx = tid & 15, ty = tid >> 4;
    const int nkt = (K + KT - 1) / KT;

    ull acc[4][2] = {};
    float rw[4]; float4 vx;
    {
#pragma unroll
        for (int s = 0; s < 4; s++) {
            int k = kb0 + s;
            rw[s] = (k < K) ? W[(size_t)o_l * K + k] : 0.f;
        }
        const float* row = (kx < C1) ? S1 + (size_t)b * s1BS + (size_t)kx * NP
                                     : S2 + (size_t)b * s2BS + (size_t)(kx - C1) * NP;
        vx = *(const float4*)(row + n0 + nc);
    }

    int buf = 0;
    for (int kt = 0; kt < nkt; kt++) {
        ull* Ad = sAp + buf * (KT * 64);
        float* Bd = sB + buf * (KT * 64);
        Ad[(kb0+0)*64+o_l] = pack2(rw[0], rw[0]);
        Ad[(kb0+1)*64+o_l] = pack2(rw[1], rw[1]);
        Ad[(kb0+2)*64+o_l] = pack2(rw[2], rw[2]);
        Ad[(kb0+3)*64+o_l] = pack2(rw[3], rw[3]);
        *(float4*)(Bd + kx * 64 + nc) = vx;
        __syncthreads();
        if (kt + 1 < nkt) {
            int kb = (kt + 1) * KT;
#pragma unroll
            for (int s = 0; s < 4; s++) {
                int k = kb + kb0 + s;
                rw[s] = (k < K) ? W[(size_t)o_l * K + k] : 0.f;
            }
            int kg = kb + kx;
            const float* row = (kg < C1) ? S1 + (size_t)b * s1BS + (size_t)kg * NP
                                         : S2 + (size_t)b * s2BS + (size_t)(kg - C1) * NP;
            vx = *(const float4*)(row + n0 + nc);
        }
        mmtile(Ad, Bd, acc, tx, ty);
        buf ^= 1;
    }

#pragma unroll
    for (int i = 0; i < 4; i++) {
        int o = ty * 4 + i;
        float bs = bias[o];
        size_t rowIdx = ((size_t)b * 64 + o) * NP + n0 + tx * 4;
#pragma unroll
        for (int j = 0; j < 2; j++) {
            int gn = n0 + tx * 4 + 2 * j;
            if (gn >= NN) continue;
            float v0, v1; unpack2(acc[i][j], v0, v1);
            v0 += bs; v1 += bs;
            if (mode == 0) {
                *(float2*)(dst + rowIdx + 2 * j) = make_float2(v0, v1);
            } else if (mode == 1) {
                float o0 = v0 >= 0.f ? v0 : pav * v0;
                float o1 = v1 >= 0.f ? v1 : pav * v1;
                *(float2*)(g_OUT + rowIdx + 2 * j) = make_float2(o0, o1);
                size_t rb = (((size_t)b * 128 + o) * NN + gn) * TT + t;
                reps[rb] = o0; reps[rb + TT] = o1;
            } else if (mode == 2) {
                *(float2*)(g_U + rowIdx + 2 * j) =
                    make_float2(1.f / (1.f + expf(-v0)), 1.f / (1.f + expf(-v1)));
            } else if (mode == 3) {
                float2 h2 = *(const float2*)(g_H + rowIdx + 2 * j);
                *(float2*)(g_CG5 + ((size_t)b * XGC + 2 + o) * NP + n0 + tx * 4 + 2 * j) =
                    make_float2(h2.x / (1.f + expf(-v0)), h2.y / (1.f + expf(-v1)));
            } else {
                float c0 = tanhf(v0), c1 = tanhf(v1);
                float2 u2 = *(const float2*)(g_U + rowIdx + 2 * j);
                float2 h2 = *(const float2*)(g_H + rowIdx + 2 * j);
                *(float2*)(g_H + rowIdx + 2 * j) =
                    make_float2(u2.x * h2.x + (1.f - u2.x) * c0,
                                u2.y * h2.y + (1.f - u2.y) * c1);
            }
        }
    }
    __syncthreads();
}

__global__ void __launch_bounds__(256, 2) kmain(
    const float* __restrict__ x, const float* __restrict__ af,
    const float* __restrict__ ab, const int* __restrict__ mask,
    const float* __restrict__ Wr,  const float* __restrict__ br,
    const float* __restrict__ Wu,  const float* __restrict__ bu,
    const float* __restrict__ Wc,  const float* __restrict__ bc,
    const float* __restrict__ Wfs, const float* __restrict__ bfs,
    const float* __restrict__ Wli, const float* __restrict__ bli,
    const float* __restrict__ Wgc, const float* __restrict__ bgc,
    const float* __restrict__ Wlo, const float* __restrict__ blo,
    const float* __restrict__ Wro, const float* __restrict__ bro,
    const float* __restrict__ pa,
    float* __restrict__ imp, float* __restrict__ pred, float* __restrict__ reps)
{
    __shared__ __align__(16) ull   sAp[2 * KT * 64];
    __shared__ __align__(16) float sB [2 * KT * 64];

    const int tid = threadIdx.x;
    const int nb = gridDim.x;
    const int gtid = blockIdx.x * 256 + tid;
    const int gstr = nb * 256;
    const float pav = *pa;

    // prologue: zero H; fold W_gc into W_lo (combined K=192 conv)
    for (int i = gtid; i < BB * 64 * NP; i += gstr) g_H[i] = 0.f;
    for (int i = gtid; i < 64 * 192; i += gstr) {
        int o = i / 192, k = i - o * 192;
        float s;
        if (k < 128) {
            s = 0.f;
            for (int j = 0; j < 64; j++) s += Wlo[o * 128 + j] * Wgc[j * 128 + k];
        } else s = Wlo[o * 128 + 64 + (k - 128)];
        g_Wc2[i] = s;
    }
    for (int i = gtid; i < 64; i += gstr) {
        float s = blo[i];
        for (int j = 0; j < 64; j++) s += Wlo[i * 128 + j] * bgc[j];
        g_bc2[i] = s;
    }
    gridbar();

    for (int t = 0; t < TT; t++) {
        // stage A: pred, x1, mf; pack XG5[0..65]; CG5[1]=mf; reps h-half
        for (int i = gtid; i < BB * NN; i += gstr) {
            int b = i / NN, n = i - b * NN;
            const float* h = g_H + (size_t)b * 64 * NP + n;
            float* xg = g_XG5 + (size_t)b * XGC * NP + n;
            float* rb = reps + (((size_t)b * 128 + 64) * NN + n) * TT + t;
            float s = bfs[0];
#pragma unroll 8
            for (int c = 0; c < 64; c++) {
                float hv = h[(size_t)c * NP];
                s += Wfs[c] * hv;
                xg[(size_t)(2 + c) * NP] = hv;
                rb[(size_t)c * NN * TT] = hv;
            }
            size_t xi = ((size_t)b * NN + n) * TT + t;
            pred[xi] = s;
            int mk = mask[xi];
            xg[0]  = mk ? x[xi] : s;
            xg[NP] = (float)mk;
            g_CG5[(size_t)b * XGC * NP + NP + n] = (float)mk;
        }
        gridbar();

        // conv li: XG5[0..65] -> XIN
        for (int tile = blockIdx.x; tile < 128; tile += nb)
            conv_tile(g_XG5, 1000, (size_t)XGC * NP, g_XG5, 0, Wli, bli, 66,
                      tile >> 3, (tile & 7) * 64, 0, g_XIN, reps, t, pav, sAp, sB);
        gridbar();

        // diffusion XIN -> XIN2 (Df | Db)
        for (int tile = blockIdx.x; tile < 256; tile += nb) {
            int z = tile >> 7, rem = tile & 127;
            diff_tile(g_XIN, g_XIN2, z ? ab : af, 64, 0, z * 64,
                      (size_t)64 * NP, (size_t)128 * NP,
                      (rem >> 3) * 64, (rem & 7) * 64, sAp, sB);
        }
        gridbar();

        // combined gc∘lo conv: [XIN2(128), H(64)] K=192 -> OUT (prelu) + reps
        for (int tile = blockIdx.x; tile < 128; tile += nb)
            conv_tile(g_XIN2, 128, (size_t)128 * NP, g_H, (size_t)64 * NP,
                      g_Wc2, g_bc2, 192,
                      tile >> 3, (tile & 7) * 64, 1, g_OUT, reps, t, pav, sAp, sB);
        gridbar();

        // stage B: imp, x2 -> XG5[0], CG5[0]
        for (int i = gtid; i < BB * NN; i += gstr) {
            int b = i / NN, n = i - b * NN;
            const float* o = g_OUT + (size_t)b * 64 * NP + n;
            const float* h = g_H   + (size_t)b * 64 * NP + n;
            float s = bro[0];
#pragma unroll 8
            for (int c = 0; c < 64; c++)
                s += Wro[c] * o[(size_t)c * NP] + Wro[64 + c] * h[(size_t)c * NP];
            size_t xi = ((size_t)b * NN + n) * TT + t;
            imp[xi] = s;
            int mk = mask[xi];
            float* xg0 = g_XG5 + (size_t)b * XGC * NP + n;
            float x2 = mk ? *xg0 : s;
            *xg0 = x2;
            g_CG5[(size_t)b * XGC * NP + n] = x2;
        }
        gridbar();

        // diffusion XG order-2 (two hops)
        for (int tile = blockIdx.x; tile < 272; tile += nb) {
            int z = tile / 136, rem = tile - z * 136;
            diff_tile(g_XG5, g_XG5, z ? ab : af, 66, 0, 66 + z * 132,
                      (size_t)XGC * NP, (size_t)XGC * NP,
                      (rem >> 3) * 64, (rem & 7) * 64, sAp, sB);
        }
        gridbar();
        for (int tile = blockIdx.x; tile < 272; tile += nb) {
            int z = tile / 136, rem = tile - z * 136;
            diff_tile(g_XG5, g_XG5, z ? ab : af, 66, 66 + z * 132, 132 + z * 132,
                      (size_t)XGC * NP, (size_t)XGC * NP,
                      (rem >> 3) * 64, (rem & 7) * 64, sAp, sB);
        }
        gridbar();

        // convs r (-> r*h into CG5[2..65]) and u (-> U)
        for (int tile = blockIdx.x; tile < 256; tile += nb) {
            int tl = tile & 127;
            if (tile < 128)
                conv_tile(g_XG5, 1000, (size_t)XGC * NP, g_XG5, 0, Wr, br, 330,
                          tl >> 3, (tl & 7) * 64, 3, g_U, reps, t, pav, sAp, sB);
            else
                conv_tile(g_XG5, 1000, (size_t)XGC * NP, g_XG5, 0, Wu, bu, 330,
                          tl >> 3, (tl & 7) * 64, 2, g_U, reps, t, pav, sAp, sB);
        }
        gridbar();

        // diffusion CG order-2 (two hops)
        for (int tile = blockIdx.x; tile < 272; tile += nb) {
            int z = tile / 136, rem = tile - z * 136;
            diff_tile(g_CG5, g_CG5, z ? ab : af, 66, 0, 66 + z * 132,
                      (size_t)XGC * NP, (size_t)XGC * NP,
                      (rem >> 3) * 64, (rem & 7) * 64, sAp, sB);
        }
        gridbar();
        for (int tile = blockIdx.x; tile < 272; tile += nb) {
            int z = tile / 136, rem = tile - z * 136;
            diff_tile(g_CG5, g_CG5, z ? ab : af, 66, 66 + z * 132, 132 + z * 132,
                      (size_t)XGC * NP, (size_t)XGC * NP,
                      (rem >> 3) * 64, (rem & 7) * 64, sAp, sB);
        }
        gridbar();

        // conv c: tanh + h = u*h + (1-u)*c
        for (int tile = blockIdx.x; tile < 128; tile += nb)
            conv_tile(g_CG5, 1000, (size_t)XGC * NP, g_CG5, 0, Wc, bc, 330,
                      tile >> 3, (tile & 7) * 64, 4, g_U, reps, t, pav, sAp, sB);
        gridbar();
    }
}

extern "C" void kernel_launch(void* const* d_in, const int* in_sizes, int n_in,
                              void* d_out, int out_size)
{
    const float* x    = (const float*)d_in[0];
    const float* af   = (const float*)d_in[1];
    const float* ab   = (const float*)d_in[2];
    const int*   mask = (const int*)  d_in[3];
    const float* Wr   = (const float*)d_in[4];
    const float* br   = (const float*)d_in[5];
    const float* Wu   = (const float*)d_in[6];
    const float* bu   = (const float*)d_in[7];
    const float* Wc   = (const float*)d_in[8];
    const float* bc   = (const float*)d_in[9];
    const float* Wfs  = (const float*)d_in[10];
    const float* bfs  = (const float*)d_in[11];
    const float* Wli  = (const float*)d_in[12];
    const float* bli  = (const float*)d_in[13];
    const float* Wgc  = (const float*)d_in[14];
    const float* bgc  = (const float*)d_in[15];
    const float* Wlo  = (const float*)d_in[16];
    const float* blo  = (const float*)d_in[17];
    const float* Wro  = (const float*)d_in[18];
    const float* bro  = (const float*)d_in[19];
    const float* pa   = (const float*)d_in[20];

    float* out_imp  = (float*)d_out;
    float* out_pred = out_imp + (size_t)BB * NN * TT;
    float* out_reps = out_imp + (size_t)2 * BB * NN * TT;

    int dev = 0; cudaGetDevice(&dev);
    int sm = 0;
    cudaDeviceGetAttribute(&sm, cudaDevAttrMultiProcessorCount, dev);
    if (sm <= 0) sm = 148;
    int per = 0;
    cudaOccupancyMaxActiveBlocksPerMultiprocessor(&per, kmain, 256, 0);
    if (per < 1) per = 1;
    if (per > 2) per = 2;
    int nb = sm * per;

    kmain<<<nb, 256>>>(x, af, ab, mask, Wr, br, Wu, bu, Wc, bc,
                       Wfs, bfs, Wli, bli, Wgc, bgc, Wlo, blo, Wro, bro, pa,
                       out_imp, out_pred, out_reps);
}

// round 8
// speedup vs baseline: 1.2023x; 1.0625x over previous
#include <cuda_runtime.h>
#include <math.h>

typedef unsigned long long ull;

#define BB 16
#define NN 500
#define TT 128
#define NP 512
#define XGC 336
#define KT 16

__device__ float g_H   [BB*64 *NP];
__device__ float g_XG5 [BB*XGC*NP];
__device__ float g_CG5 [BB*XGC*NP];
__device__ float g_XIN [BB*64 *NP];
__device__ float g_XIN2[BB*128*NP];
__device__ float g_OUT [BB*64 *NP];
__device__ float g_U   [BB*64 *NP];
__device__ float g_Wc2 [64*192];
__device__ float g_bc2 [64];

__device__ unsigned g_cnt;
__device__ volatile unsigned g_gen;

__device__ __forceinline__ ull pack2(float x, float y) {
    ull r; asm("mov.b64 %0, {%1,%2};" : "=l"(r) : "f"(x), "f"(y)); return r;
}
__device__ __forceinline__ void unpack2(ull p, float& x, float& y) {
    asm("mov.b64 {%0,%1}, %2;" : "=f"(x), "=f"(y) : "l"(p));
}
__device__ __forceinline__ void fma2(ull& d, ull a, ull b) {
    asm("fma.rn.f32x2 %0, %1, %2, %0;" : "+l"(d) : "l"(a), "l"(b));
}

__device__ __forceinline__ void gridbar() {
    __syncthreads();
    if (threadIdx.x == 0) {
        unsigned gen = g_gen;
        __threadfence();
        if (atomicAdd(&g_cnt, 1u) == gridDim.x - 1u) {
            atomicExch(&g_cnt, 0u);
            __threadfence();
            g_gen = gen + 1u;
        } else {
            while (g_gen == gen) __nanosleep(200);
        }
        __threadfence();
    }
    __syncthreads();
}

// 64x64 tile, 128 threads. tx=tid&15 (4 n), ty=tid>>4 (8 m).
// As float[k][64] plain, Bs float[k][64] plain.
__device__ __forceinline__ void mmtile(const float* __restrict__ As,
                                       const float* __restrict__ Bs,
                                       ull acc[8][2], int tx, int ty)
{
#pragma unroll
    for (int kk = 0; kk < KT; kk++) {
        float4 a0 = *(const float4*)(As + kk * 64 + ty * 8);
        float4 a1 = *(const float4*)(As + kk * 64 + ty * 8 + 4);
        ulonglong2 B0 = *(const ulonglong2*)((const ull*)(Bs + kk * 64) + tx * 2);
        ull ap;
        ap = pack2(a0.x, a0.x); fma2(acc[0][0], ap, B0.x); fma2(acc[0][1], ap, B0.y);
        ap = pack2(a0.y, a0.y); fma2(acc[1][0], ap, B0.x); fma2(acc[1][1], ap, B0.y);
        ap = pack2(a0.z, a0.z); fma2(acc[2][0], ap, B0.x); fma2(acc[2][1], ap, B0.y);
        ap = pack2(a0.w, a0.w); fma2(acc[3][0], ap, B0.x); fma2(acc[3][1], ap, B0.y);
        ap = pack2(a1.x, a1.x); fma2(acc[4][0], ap, B0.x); fma2(acc[4][1], ap, B0.y);
        ap = pack2(a1.y, a1.y); fma2(acc[5][0], ap, B0.x); fma2(acc[5][1], ap, B0.y);
        ap = pack2(a1.z, a1.z); fma2(acc[6][0], ap, B0.x); fma2(acc[6][1], ap, B0.y);
        ap = pack2(a1.w, a1.w); fma2(acc[7][0], ap, B0.x); fma2(acc[7][1], ap, B0.y);
    }
}

// dst[b, dstOff+c, w] = sum_v src[b, srcOff+c, v] * A[w, v]
__device__ void diff_tile(const float* __restrict__ src, float* __restrict__ dst,
                          const float* __restrict__ A,
                          int C, int srcOff, int dstOff, size_t srcBS, size_t dstBS,
                          int m0, int n0, float* sA, float* sB)
{
    const int tid = threadIdx.x;
    const int r = tid & 63, kseg = (tid >> 6) * 8;
    const int tx = tid & 15, ty = tid >> 4;
    const int M = C * BB;

    const float* srow = 0;
    { int gm = m0 + r;
      if (gm < M) { int b = gm / C, c = gm - b * C;
          srow = src + (size_t)b * srcBS + (size_t)(srcOff + c) * NP; } }
    const float* arow = 0;
    { int gn = n0 + r; if (gn < NN) arow = A + (size_t)gn * NN; }

    ull acc[8][2] = {};
    const float4 Z = make_float4(0.f, 0.f, 0.f, 0.f);
#define LDA(kb) (srow ? *(const float4*)(srow + (kb)) : Z)
#define LDB(kb) ((arow && (kb) < NN) ? *(const float4*)(arow + (kb)) : Z)
    const int nkt = NP / KT;   // 32
    float4 pa0 = LDA(kseg), pa1 = LDA(kseg + 4);
    float4 pb0 = LDB(kseg), pb1 = LDB(kseg + 4);
    float4 qa0 = LDA(KT + kseg), qa1 = LDA(KT + kseg + 4);
    float4 qb0 = LDB(KT + kseg), qb1 = LDB(KT + kseg + 4);

    for (int kt = 0; kt < nkt; kt++) {
        float* Ad = sA + (kt & 1) * (KT * 64);
        float* Bd = sB + (kt & 1) * (KT * 64);
        Ad[(kseg+0)*64+r] = pa0.x; Ad[(kseg+1)*64+r] = pa0.y;
        Ad[(kseg+2)*64+r] = pa0.z; Ad[(kseg+3)*64+r] = pa0.w;
        Ad[(kseg+4)*64+r] = pa1.x; Ad[(kseg+5)*64+r] = pa1.y;
        Ad[(kseg+6)*64+r] = pa1.z; Ad[(kseg+7)*64+r] = pa1.w;
        Bd[(kseg+0)*64+r] = pb0.x; Bd[(kseg+1)*64+r] = pb0.y;
        Bd[(kseg+2)*64+r] = pb0.z; Bd[(kseg+3)*64+r] = pb0.w;
        Bd[(kseg+4)*64+r] = pb1.x; Bd[(kseg+5)*64+r] = pb1.y;
        Bd[(kseg+6)*64+r] = pb1.z; Bd[(kseg+7)*64+r] = pb1.w;
        __syncthreads();
        pa0 = qa0; pa1 = qa1; pb0 = qb0; pb1 = qb1;
        if (kt + 2 < nkt) {
            int kb = (kt + 2) * KT + kseg;
            qa0 = LDA(kb); qa1 = LDA(kb + 4);
            qb0 = LDB(kb); qb1 = LDB(kb + 4);
        }
        mmtile(Ad, Bd, acc, tx, ty);
    }
#undef LDA
#undef LDB

#pragma unroll
    for (int i = 0; i < 8; i++) {
        int gm = m0 + ty * 8 + i;
        if (gm >= M) continue;
        int b = gm / C, c = gm - b * C;
        int gn = n0 + tx * 4;
        if (gn >= NN) continue;
        float* drow = dst + (size_t)b * dstBS + (size_t)(dstOff + c) * NP + gn;
        float v0, v1, v2, v3;
        unpack2(acc[i][0], v0, v1);
        unpack2(acc[i][1], v2, v3);
        *(float2*)(drow)     = make_float2(v0, v1);
        *(float2*)(drow + 2) = make_float2(v2, v3);
    }
    __syncthreads();
}

// out[b,o,n] = act(sum_k W[o,k]*X[b,k,n] + bias[o]), O=64, X=concat(S1,S2)
// mode 0: ->dst | 1: prelu->g_OUT + reps | 2: sigmoid->g_U
// mode 3: sigmoid*h->g_CG5[2+o] | 4: tanh, h=u*h+(1-u)*c
__device__ void conv_tile(const float* __restrict__ S1, int C1, size_t s1BS,
                          const float* __restrict__ S2, size_t s2BS,
                          const float* __restrict__ W, const float* __restrict__ bias,
                          int K, int b, int n0, int mode,
                          float* __restrict__ dst, float* __restrict__ reps,
                          int t, float pav, float* sA, float* sB)
{
    const int tid = threadIdx.x;
    const int o_l = tid & 63, kseg = (tid >> 6) * 8;
    const int kx = tid >> 3, nc = (tid & 7) * 8;
    const int tx = tid & 15, ty = tid >> 4;
    const int nkt = (K + KT - 1) / KT;

    ull acc[8][2] = {};
    float pw[8], qw[8];
    float4 px0, px1, qx0, qx1;

#define LDW(dstw, kt) do { \
        int kb_ = (kt) * KT + kseg; \
        _Pragma("unroll") \
        for (int s_ = 0; s_ < 8; s_++) { \
            int k_ = kb_ + s_; \
            dstw[s_] = (k_ < K) ? W[(size_t)o_l * K + k_] : 0.f; \
        } } while (0)
#define LDX(d0, d1, kt) do { \
        int kg_ = (kt) * KT + kx; \
        const float* row_ = (kg_ < C1) \
            ? S1 + (size_t)b * s1BS + (size_t)kg_ * NP \
            : S2 + (size_t)b * s2BS + (size_t)(kg_ - C1) * NP; \
        d0 = *(const float4*)(row_ + n0 + nc); \
        d1 = *(const float4*)(row_ + n0 + nc + 4); } while (0)

    LDW(pw, 0); LDX(px0, px1, 0);
    if (nkt > 1) { LDW(qw, 1); LDX(qx0, qx1, 1); }

    for (int kt = 0; kt < nkt; kt++) {
        float* Ad = sA + (kt & 1) * (KT * 64);
        float* Bd = sB + (kt & 1) * (KT * 64);
#pragma unroll
        for (int s = 0; s < 8; s++) Ad[(kseg + s) * 64 + o_l] = pw[s];
        *(float4*)(Bd + kx * 64 + nc)     = px0;
        *(float4*)(Bd + kx * 64 + nc + 4) = px1;
        __syncthreads();
#pragma unroll
        for (int s = 0; s < 8; s++) pw[s] = qw[s];
        px0 = qx0; px1 = qx1;
        if (kt + 2 < nkt) { LDW(qw, kt + 2); LDX(qx0, qx1, kt + 2); }
        mmtile(Ad, Bd, acc, tx, ty);
    }
#undef LDW
#undef LDX

#pragma unroll
    for (int i = 0; i < 8; i++) {
        int o = ty * 8 + i;
        float bs = bias[o];
        int gn = n0 + tx * 4;
        if (gn >= NN) continue;
        size_t rowIdx = ((size_t)b * 64 + o) * NP + gn;
        float v[4];
        unpack2(acc[i][0], v[0], v[1]);
        unpack2(acc[i][1], v[2], v[3]);
        if (mode == 0) {
#pragma unroll
            for (int j = 0; j < 4; j++) dst[rowIdx + j] = v[j] + bs;
        } else if (mode == 1) {
            size_t rb = (((size_t)b * 128 + o) * NN + gn) * TT + t;
#pragma unroll
            for (int j = 0; j < 4; j++) {
                float vv = v[j] + bs;
                vv = vv >= 0.f ? vv : pav * vv;
                g_OUT[rowIdx + j] = vv;
                reps[rb + (size_t)j * TT] = vv;
            }
        } else if (mode == 2) {
#pragma unroll
            for (int j = 0; j < 4; j++)
                g_U[rowIdx + j] = 1.f / (1.f + expf(-(v[j] + bs)));
        } else if (mode == 3) {
            float* cg = g_CG5 + ((size_t)b * XGC + 2 + o) * NP + gn;
#pragma unroll
            for (int j = 0; j < 4; j++)
                cg[j] = g_H[rowIdx + j] / (1.f + expf(-(v[j] + bs)));
        } else {
#pragma unroll
            for (int j = 0; j < 4; j++) {
                float cc = tanhf(v[j] + bs);
                float u = g_U[rowIdx + j];
                g_H[rowIdx + j] = u * g_H[rowIdx + j] + (1.f - u) * cc;
            }
        }
    }
    __syncthreads();
}

__global__ void __launch_bounds__(128, 3) kmain(
    const float* __restrict__ x, const float* __restrict__ af,
    const float* __restrict__ ab, const int* __restrict__ mask,
    const float* __restrict__ Wr,  const float* __restrict__ br,
    const float* __restrict__ Wu,  const float* __restrict__ bu,
    const float* __restrict__ Wc,  const float* __restrict__ bc,
    const float* __restrict__ Wfs, const float* __restrict__ bfs,
    const float* __restrict__ Wli, const float* __restrict__ bli,
    const float* __restrict__ Wgc, const float* __restrict__ bgc,
    const float* __restrict__ Wlo, const float* __restrict__ blo,
    const float* __restrict__ Wro, const float* __restrict__ bro,
    const float* __restrict__ pa,
    float* __restrict__ imp, float* __restrict__ pred, float* __restrict__ reps)
{
    __shared__ __align__(16) float sA[2 * KT * 64];
    __shared__ __align__(16) float sB[2 * KT * 64];

    const int tid = threadIdx.x;
    const int nb = gridDim.x;
    const int gtid = blockIdx.x * 128 + tid;
    const int gstr = nb * 128;
    const float pav = *pa;

    // prologue: zero H; fold W_gc into W_lo (combined K=192 conv)
    for (int i = gtid; i < BB * 64 * NP; i += gstr) g_H[i] = 0.f;
    for (int i = gtid; i < 64 * 192; i += gstr) {
        int o = i / 192, k = i - o * 192;
        float s;
        if (k < 128) {
            s = 0.f;
            for (int j = 0; j < 64; j++) s += Wlo[o * 128 + j] * Wgc[j * 128 + k];
        } else s = Wlo[o * 128 + 64 + (k - 128)];
        g_Wc2[i] = s;
    }
    for (int i = gtid; i < 64; i += gstr) {
        float s = blo[i];
        for (int j = 0; j < 64; j++) s += Wlo[i * 128 + j] * bgc[j];
        g_bc2[i] = s;
    }
    gridbar();

    for (int t = 0; t < TT; t++) {
        // stage A: pred, x1, mf; pack XG5[0..65]; CG5[1]=mf; reps h-half
        for (int i = gtid; i < BB * NN; i += gstr) {
            int b = i / NN, n = i - b * NN;
            const float* h = g_H + (size_t)b * 64 * NP + n;
            float* xg = g_XG5 + (size_t)b * XGC * NP + n;
            float* rb = reps + (((size_t)b * 128 + 64) * NN + n) * TT + t;
            float s = bfs[0];
#pragma unroll 8
            for (int c = 0; c < 64; c++) {
                float hv = h[(size_t)c * NP];
                s += Wfs[c] * hv;
                xg[(size_t)(2 + c) * NP] = hv;
                rb[(size_t)c * NN * TT] = hv;
            }
            size_t xi = ((size_t)b * NN + n) * TT + t;
            pred[xi] = s;
            int mk = mask[xi];
            xg[0]  = mk ? x[xi] : s;
            xg[NP] = (float)mk;
            g_CG5[(size_t)b * XGC * NP + NP + n] = (float)mk;
        }
        gridbar();

        // conv li: XG5[0..65] -> XIN
        for (int tile = blockIdx.x; tile < 128; tile += nb)
            conv_tile(g_XG5, 1000, (size_t)XGC * NP, g_XG5, 0, Wli, bli, 66,
                      tile >> 3, (tile & 7) * 64, 0, g_XIN, reps, t, pav, sA, sB);
        gridbar();

        // diffusion XIN -> XIN2 (Df | Db)
        for (int tile = blockIdx.x; tile < 256; tile += nb) {
            int z = tile >> 7, rem = tile & 127;
            diff_tile(g_XIN, g_XIN2, z ? ab : af, 64, 0, z * 64,
                      (size_t)64 * NP, (size_t)128 * NP,
                      (rem >> 3) * 64, (rem & 7) * 64, sA, sB);
        }
        gridbar();

        // combined gc∘lo conv: [XIN2(128), H(64)] K=192 -> OUT (prelu) + reps
        for (int tile = blockIdx.x; tile < 128; tile += nb)
            conv_tile(g_XIN2, 128, (size_t)128 * NP, g_H, (size_t)64 * NP,
                      g_Wc2, g_bc2, 192,
                      tile >> 3, (tile & 7) * 64, 1, g_OUT, reps, t, pav, sA, sB);
        gridbar();

        // stage B: imp, x2 -> XG5[0], CG5[0]
        for (int i = gtid; i < BB * NN; i += gstr) {
            int b = i / NN, n = i - b * NN;
            const float* o = g_OUT + (size_t)b * 64 * NP + n;
            const float* h = g_H   + (size_t)b * 64 * NP + n;
            float s = bro[0];
#pragma unroll 8
            for (int c = 0; c < 64; c++)
                s += Wro[c] * o[(size_t)c * NP] + Wro[64 + c] * h[(size_t)c * NP];
            size_t xi = ((size_t)b * NN + n) * TT + t;
            imp[xi] = s;
            int mk = mask[xi];
            float* xg0 = g_XG5 + (size_t)b * XGC * NP + n;
            float x2 = mk ? *xg0 : s;
            *xg0 = x2;
            g_CG5[(size_t)b * XGC * NP + n] = x2;
        }
        gridbar();

        // diffusion XG order-2 (two hops)
        for (int tile = blockIdx.x; tile < 272; tile += nb) {
            int z = tile / 136, rem = tile - z * 136;
            diff_tile(g_XG5, g_XG5, z ? ab : af, 66, 0, 66 + z * 132,
                      (size_t)XGC * NP, (size_t)XGC * NP,
                      (rem >> 3) * 64, (rem & 7) * 64, sA, sB);
        }
        gridbar();
        for (int tile = blockIdx.x; tile < 272; tile += nb) {
            int z = tile / 136, rem = tile - z * 136;
            diff_tile(g_XG5, g_XG5, z ? ab : af, 66, 66 + z * 132, 132 + z * 132,
                      (size_t)XGC * NP, (size_t)XGC * NP,
                      (rem >> 3) * 64, (rem & 7) * 64, sA, sB);
        }
        gridbar();

        // convs r (-> r*h into CG5[2..65]) and u (-> U)
        for (int tile = blockIdx.x; tile < 256; tile += nb) {
            int tl = tile & 127;
            if (tile < 128)
                conv_tile(g_XG5, 1000, (size_t)XGC * NP, g_XG5, 0, Wr, br, 330,
                          tl >> 3, (tl & 7) * 64, 3, g_U, reps, t, pav, sA, sB);
            else
                conv_tile(g_XG5, 1000, (size_t)XGC * NP, g_XG5, 0, Wu, bu, 330,
                          tl >> 3, (tl & 7) * 64, 2, g_U, reps, t, pav, sA, sB);
        }
        gridbar();

        // diffusion CG order-2 (two hops)
        for (int tile = blockIdx.x; tile < 272; tile += nb) {
            int z = tile / 136, rem = tile - z * 136;
            diff_tile(g_CG5, g_CG5, z ? ab : af, 66, 0, 66 + z * 132,
                      (size_t)XGC * NP, (size_t)XGC * NP,
                      (rem >> 3) * 64, (rem & 7) * 64, sA, sB);
        }
        gridbar();
        for (int tile = blockIdx.x; tile < 272; tile += nb) {
            int z = tile / 136, rem = tile - z * 136;
            diff_tile(g_CG5, g_CG5, z ? ab : af, 66, 66 + z * 132, 132 + z * 132,
                      (size_t)XGC * NP, (size_t)XGC * NP,
                      (rem >> 3) * 64, (rem & 7) * 64, sA, sB);
        }
        gridbar();

        // conv c: tanh + h = u*h + (1-u)*c
        for (int tile = blockIdx.x; tile < 128; tile += nb)
            conv_tile(g_CG5, 1000, (size_t)XGC * NP, g_CG5, 0, Wc, bc, 330,
                      tile >> 3, (tile & 7) * 64, 4, g_U, reps, t, pav, sA, sB);
        gridbar();
    }
}

extern "C" void kernel_launch(void* const* d_in, const int* in_sizes, int n_in,
                              void* d_out, int out_size)
{
    const float* x    = (const float*)d_in[0];
    const float* af   = (const float*)d_in[1];
    const float* ab   = (const float*)d_in[2];
    const int*   mask = (const int*)  d_in[3];
    const float* Wr   = (const float*)d_in[4];
    const float* br   = (const float*)d_in[5];
    const float* Wu   = (const float*)d_in[6];
    const float* bu   = (const float*)d_in[7];
    const float* Wc   = (const float*)d_in[8];
    const float* bc   = (const float*)d_in[9];
    const float* Wfs  = (const float*)d_in[10];
    const float* bfs  = (const float*)d_in[11];
    const float* Wli  = (const float*)d_in[12];
    const float* bli  = (const float*)d_in[13];
    const float* Wgc  = (const float*)d_in[14];
    const float* bgc  = (const float*)d_in[15];
    const float* Wlo  = (const float*)d_in[16];
    const float* blo  = (const float*)d_in[17];
    const float* Wro  = (const float*)d_in[18];
    const float* bro  = (const float*)d_in[19];
    const float* pa   = (const float*)d_in[20];

    float* out_imp  = (float*)d_out;
    float* out_pred = out_imp + (size_t)BB * NN * TT;
    float* out_reps = out_imp + (size_t)2 * BB * NN * TT;

    int dev = 0; cudaGetDevice(&dev);
    int sm = 0;
    cudaDeviceGetAttribute(&sm, cudaDevAttrMultiProcessorCount, dev);
    if (sm <= 0) sm = 148;
    int per = 0;
    cudaOccupancyMaxActiveBlocksPerMultiprocessor(&per, kmain, 128, 0);
    if (per < 1) per = 1;
    if (per > 3) per = 3;
    int nb = sm * per;

    kmain<<<nb, 128>>>(x, af, ab, mask, Wr, br, Wu, bu, Wc, bc,
                       Wfs, bfs, Wli, bli, Wgc, bgc, Wlo, blo, Wro, bro, pa,
                       out_imp, out_pred, out_reps);
}

// round 9
// speedup vs baseline: 1.2820x; 1.0663x over previous
#include <cuda_runtime.h>
#include <math.h>

typedef unsigned long long ull;

#define BB 16
#define NN 500
#define TT 128
#define NP 512
#define XGC 336
#define KT 16

__device__ float g_H   [BB*64 *NP];
__device__ float g_XG5 [BB*XGC*NP];
__device__ float g_CG5 [BB*XGC*NP];
__device__ float g_XIN [BB*64 *NP];
__device__ float g_XIN2[BB*128*NP];
__device__ float g_U   [BB*64 *NP];
__device__ float g_A2f [512*512];
__device__ float g_A2b [512*512];
__device__ float g_Wc2 [64*192];
__device__ float g_bc2 [64];

__device__ unsigned g_cnt;
__device__ volatile unsigned g_gen;

__device__ __forceinline__ ull pack2(float x, float y) {
    ull r; asm("mov.b64 %0, {%1,%2};" : "=l"(r) : "f"(x), "f"(y)); return r;
}
__device__ __forceinline__ void unpack2(ull p, float& x, float& y) {
    asm("mov.b64 {%0,%1}, %2;" : "=f"(x), "=f"(y) : "l"(p));
}
__device__ __forceinline__ void fma2(ull& d, ull a, ull b) {
    asm("fma.rn.f32x2 %0, %1, %2, %0;" : "+l"(d) : "l"(a), "l"(b));
}

__device__ __forceinline__ void gridbar() {
    __syncthreads();
    if (threadIdx.x == 0) {
        unsigned gen = g_gen;
        __threadfence();
        if (atomicAdd(&g_cnt, 1u) == gridDim.x - 1u) {
            atomicExch(&g_cnt, 0u);
            __threadfence();
            g_gen = gen + 1u;
        } else {
            while (g_gen == gen) __nanosleep(64);
        }
        __threadfence();
    }
    __syncthreads();
}

// ---- micro-kernels -----------------------------------------------------------
// 128m x 64n, 256 threads: tx=tid&15 (4 n), ty=tid>>4 (8 m)
__device__ __forceinline__ void mm_diff(const float* __restrict__ As,
                                        const float* __restrict__ Bs,
                                        ull acc[8][2], int tx, int ty)
{
#pragma unroll
    for (int kk = 0; kk < KT; kk++) {
        float4 a0 = *(const float4*)(As + kk * 128 + ty * 8);
        float4 a1 = *(const float4*)(As + kk * 128 + ty * 8 + 4);
        ulonglong2 B0 = *(const ulonglong2*)((const ull*)(Bs + kk * 64) + tx * 2);
        ull ap;
        ap = pack2(a0.x, a0.x); fma2(acc[0][0], ap, B0.x); fma2(acc[0][1], ap, B0.y);
        ap = pack2(a0.y, a0.y); fma2(acc[1][0], ap, B0.x); fma2(acc[1][1], ap, B0.y);
        ap = pack2(a0.z, a0.z); fma2(acc[2][0], ap, B0.x); fma2(acc[2][1], ap, B0.y);
        ap = pack2(a0.w, a0.w); fma2(acc[3][0], ap, B0.x); fma2(acc[3][1], ap, B0.y);
        ap = pack2(a1.x, a1.x); fma2(acc[4][0], ap, B0.x); fma2(acc[4][1], ap, B0.y);
        ap = pack2(a1.y, a1.y); fma2(acc[5][0], ap, B0.x); fma2(acc[5][1], ap, B0.y);
        ap = pack2(a1.z, a1.z); fma2(acc[6][0], ap, B0.x); fma2(acc[6][1], ap, B0.y);
        ap = pack2(a1.w, a1.w); fma2(acc[7][0], ap, B0.x); fma2(acc[7][1], ap, B0.y);
    }
}

// 64o x 128n, 256 threads: tx=tid&15 (8 n), ty=tid>>4 (4 o)
__device__ __forceinline__ void mm_conv(const float* __restrict__ As,
                                        const float* __restrict__ Bs,
                                        ull acc[4][4], int tx, int ty)
{
#pragma unroll
    for (int kk = 0; kk < KT; kk++) {
        float4 a = *(const float4*)(As + kk * 64 + ty * 4);
        const ull* br = (const ull*)(Bs + kk * 128) + tx * 4;
        ulonglong2 B0 = *(const ulonglong2*)br;
        ulonglong2 B1 = *(const ulonglong2*)(br + 2);
        ull ap;
        ap = pack2(a.x, a.x);
        fma2(acc[0][0], ap, B0.x); fma2(acc[0][1], ap, B0.y);
        fma2(acc[0][2], ap, B1.x); fma2(acc[0][3], ap, B1.y);
        ap = pack2(a.y, a.y);
        fma2(acc[1][0], ap, B0.x); fma2(acc[1][1], ap, B0.y);
        fma2(acc[1][2], ap, B1.x); fma2(acc[1][3], ap, B1.y);
        ap = pack2(a.z, a.z);
        fma2(acc[2][0], ap, B0.x); fma2(acc[2][1], ap, B0.y);
        fma2(acc[2][2], ap, B1.x); fma2(acc[2][3], ap, B1.y);
        ap = pack2(a.w, a.w);
        fma2(acc[3][0], ap, B0.x); fma2(acc[3][1], ap, B0.y);
        fma2(acc[3][2], ap, B1.x); fma2(acc[3][3], ap, B1.y);
    }
}

// ---- diffusion tile: dst[b, dstOff+c, w] = sum_v src[b, srcOff+c, v]*Amat[w,v]
// Amat row stride astr; 128m x 64n tile.
__device__ void diff_tile(const float* __restrict__ src, float* __restrict__ dst,
                          const float* __restrict__ Amat, int astr,
                          int C, int srcOff, int dstOff, size_t srcBS, size_t dstBS,
                          int m0, int n0, float* sA, float* sB)
{
    const int tid = threadIdx.x;
    const int ra = tid & 127, sa = (tid >> 7) * 8;
    const int rb = tid & 63,  qb = (tid >> 6) * 4;
    const int tx = tid & 15,  ty = tid >> 4;
    const int M = C * BB;

    const float* srow = 0;
    { int gm = m0 + ra;
      if (gm < M) { int b = gm / C, c = gm - b * C;
          srow = src + (size_t)b * srcBS + (size_t)(srcOff + c) * NP; } }
    const float* arow = 0;
    { int gn = n0 + rb; if (gn < NN) arow = Amat + (size_t)gn * astr; }

    ull acc[8][2] = {};
    const float4 Z = make_float4(0.f, 0.f, 0.f, 0.f);
#define LA(kb) (srow ? *(const float4*)(srow + (kb)) : Z)
#define LB(kb) ((arow && (kb) < NN) ? *(const float4*)(arow + (kb)) : Z)
    const int nkt = NP / KT;  // 32
    float4 pa0 = LA(sa), pa1 = LA(sa + 4), pb = LB(qb);
    float4 qa0 = LA(KT + sa), qa1 = LA(KT + sa + 4), qbv = LB(KT + qb);

    for (int kt = 0; kt < nkt; kt++) {
        float* Ad = sA + (kt & 1) * 2048;
        float* Bd = sB + (kt & 1) * 1024;
        Ad[(sa+0)*128+ra] = pa0.x; Ad[(sa+1)*128+ra] = pa0.y;
        Ad[(sa+2)*128+ra] = pa0.z; Ad[(sa+3)*128+ra] = pa0.w;
        Ad[(sa+4)*128+ra] = pa1.x; Ad[(sa+5)*128+ra] = pa1.y;
        Ad[(sa+6)*128+ra] = pa1.z; Ad[(sa+7)*128+ra] = pa1.w;
        Bd[(qb+0)*64+rb] = pb.x; Bd[(qb+1)*64+rb] = pb.y;
        Bd[(qb+2)*64+rb] = pb.z; Bd[(qb+3)*64+rb] = pb.w;
        __syncthreads();
        pa0 = qa0; pa1 = qa1; pb = qbv;
        if (kt + 2 < nkt) {
            int kb = (kt + 2) * KT;
            qa0 = LA(kb + sa); qa1 = LA(kb + sa + 4); qbv = LB(kb + qb);
        }
        mm_diff(Ad, Bd, acc, tx, ty);
    }
#undef LA
#undef LB

#pragma unroll
    for (int i = 0; i < 8; i++) {
        int gm = m0 + ty * 8 + i;
        if (gm >= M) continue;
        int b = gm / C, c = gm - b * C;
        float* drow = dst + (size_t)b * dstBS + (size_t)(dstOff + c) * NP;
#pragma unroll
        for (int j = 0; j < 2; j++) {
            int gn = n0 + tx * 4 + 2 * j;
            if (gn < NN) {
                float v0, v1; unpack2(acc[i][j], v0, v1);
                *(float2*)(drow + gn) = make_float2(v0, v1);
            }
        }
    }
    __syncthreads();
}

// ---- A2 tile: dst[w,u] = sum_v A[w,v]*A[v,u]; dst stride 512 ----------------
__device__ void a2_tile(const float* __restrict__ A, float* __restrict__ dst,
                        int m0, int n0, float* sA, float* sB)
{
    const int tid = threadIdx.x;
    const int ra = tid & 127, sa = (tid >> 7) * 8;
    const int kb_row = tid >> 4, ncl = (tid & 15) * 4;
    const int tx = tid & 15, ty = tid >> 4;

    const float* srow = 0;
    { int gm = m0 + ra; if (gm < NN) srow = A + (size_t)gm * NN; }

    ull acc[8][2] = {};
    const float4 Z = make_float4(0.f, 0.f, 0.f, 0.f);
#define LA(kb) ((srow && (kb) < NN) ? *(const float4*)(srow + (kb)) : Z)
#define LB(kt) (((kt) * KT + kb_row < NN && n0 + ncl < NN) \
      ? *(const float4*)(A + (size_t)((kt) * KT + kb_row) * NN + n0 + ncl) : Z)
    const int nkt = NP / KT;
    float4 pa0 = LA(sa), pa1 = LA(sa + 4), pb = LB(0);
    float4 qa0 = LA(KT + sa), qa1 = LA(KT + sa + 4), qbv = LB(1);

    for (int kt = 0; kt < nkt; kt++) {
        float* Ad = sA + (kt & 1) * 2048;
        float* Bd = sB + (kt & 1) * 1024;
        Ad[(sa+0)*128+ra] = pa0.x; Ad[(sa+1)*128+ra] = pa0.y;
        Ad[(sa+2)*128+ra] = pa0.z; Ad[(sa+3)*128+ra] = pa0.w;
        Ad[(sa+4)*128+ra] = pa1.x; Ad[(sa+5)*128+ra] = pa1.y;
        Ad[(sa+6)*128+ra] = pa1.z; Ad[(sa+7)*128+ra] = pa1.w;
        Bd[kb_row*64+ncl+0] = pb.x; Bd[kb_row*64+ncl+1] = pb.y;
        Bd[kb_row*64+ncl+2] = pb.z; Bd[kb_row*64+ncl+3] = pb.w;
        __syncthreads();
        pa0 = qa0; pa1 = qa1; pb = qbv;
        if (kt + 2 < nkt) {
            int kb = (kt + 2) * KT;
            qa0 = LA(kb + sa); qa1 = LA(kb + sa + 4); qbv = LB(kt + 2);
        }
        mm_diff(Ad, Bd, acc, tx, ty);
    }
#undef LA
#undef LB

#pragma unroll
    for (int i = 0; i < 8; i++) {
        int gm = m0 + ty * 8 + i;
        if (gm >= NN) continue;
        float* drow = dst + (size_t)gm * 512;
#pragma unroll
        for (int j = 0; j < 2; j++) {
            int gn = n0 + tx * 4 + 2 * j;
            if (gn < NN) {
                float v0, v1; unpack2(acc[i][j], v0, v1);
                *(float2*)(drow + gn) = make_float2(v0, v1);
            }
        }
    }
    __syncthreads();
}

// ---- 1x1 conv tile 64o x 128n; modes:
// 0 plain->dst | 1 gclo: prelu->reps + fused stage-B | 2 r: sig*h->CG5[2+o]
// 3 u: sig->g_U | 4 c: tanh,h-upd + fused stage-A(t+1)
__device__ void conv_tile(const float* __restrict__ S1, int C1, size_t s1BS,
                          const float* __restrict__ S2, size_t s2BS,
                          const float* __restrict__ W, const float* __restrict__ bias,
                          int K, int b, int n0, int mode, int t, float pav,
                          float* __restrict__ dst,
                          const float* __restrict__ Wv, const float* __restrict__ bv,
                          const float* __restrict__ x, const int* __restrict__ mask,
                          float* __restrict__ imp, float* __restrict__ pred,
                          float* __restrict__ reps,
                          float* sA, float* sB, float* sRed)
{
    const int tid = threadIdx.x;
    const int ow = tid & 63, kq = (tid >> 6) * 4;
    const int kxl = tid >> 4, ncl = (tid & 15) * 8;
    const int tx = tid & 15, ty = tid >> 4;
    const int nkt = (K + KT - 1) / KT;

    ull acc[4][4] = {};
    float pw[4], qw[4];
    float4 px0, px1, qx0, qx1;

#define LW(dw, kt) do { \
        int kb_ = (kt) * KT + kq; \
        _Pragma("unroll") \
        for (int s_ = 0; s_ < 4; s_++) { \
            int k_ = kb_ + s_; \
            dw[s_] = (k_ < K) ? W[(size_t)ow * K + k_] : 0.f; \
        } } while (0)
#define LX(d0, d1, kt) do { \
        int kg_ = (kt) * KT + kxl; \
        const float* row_ = (kg_ < C1) \
            ? S1 + (size_t)b * s1BS + (size_t)kg_ * NP \
            : S2 + (size_t)b * s2BS + (size_t)(kg_ - C1) * NP; \
        d0 = *(const float4*)(row_ + n0 + ncl); \
        d1 = *(const float4*)(row_ + n0 + ncl + 4); } while (0)

    LW(pw, 0); LX(px0, px1, 0);
    if (nkt > 1) { LW(qw, 1); LX(qx0, qx1, 1); }

    for (int kt = 0; kt < nkt; kt++) {
        float* Ad = sA + (kt & 1) * 1024;
        float* Bd = sB + (kt & 1) * 2048;
        Ad[(kq+0)*64+ow] = pw[0]; Ad[(kq+1)*64+ow] = pw[1];
        Ad[(kq+2)*64+ow] = pw[2]; Ad[(kq+3)*64+ow] = pw[3];
        *(float4*)(Bd + kxl * 128 + ncl)     = px0;
        *(float4*)(Bd + kxl * 128 + ncl + 4) = px1;
        __syncthreads();
        pw[0]=qw[0]; pw[1]=qw[1]; pw[2]=qw[2]; pw[3]=qw[3];
        px0 = qx0; px1 = qx1;
        if (kt + 2 < nkt) { LW(qw, kt + 2); LX(qx0, qx1, kt + 2); }
        mm_conv(Ad, Bd, acc, tx, ty);
    }
#undef LW
#undef LX

    float p[8];
#pragma unroll
    for (int j = 0; j < 8; j++) p[j] = 0.f;
    const bool wr = (t + 1 < TT);   // used by mode 4

#pragma unroll
    for (int i = 0; i < 4; i++) {
        int o = ty * 4 + i;
        float bs = bias[o];
        size_t rowB = ((size_t)b * 64 + o) * NP;
#pragma unroll
        for (int q = 0; q < 4; q++) {
            int gn = n0 + tx * 8 + 2 * q;
            if (gn >= NN) continue;
            float v0, v1; unpack2(acc[i][q], v0, v1);
            v0 += bs; v1 += bs;
            if (mode == 0) {
                *(float2*)(dst + rowB + gn) = make_float2(v0, v1);
            } else if (mode == 1) {
                float o0 = v0 >= 0.f ? v0 : pav * v0;
                float o1 = v1 >= 0.f ? v1 : pav * v1;
                size_t rb = (((size_t)b * 128 + o) * NN + gn) * TT + t;
                reps[rb] = o0; reps[rb + TT] = o1;
                float2 h2 = *(const float2*)(g_H + rowB + gn);
                float wo = Wv[o], wh = Wv[64 + o];
                p[2*q]   += wo * o0 + wh * h2.x;
                p[2*q+1] += wo * o1 + wh * h2.y;
            } else if (mode == 2) {
                float2 h2 = *(const float2*)(g_H + rowB + gn);
                *(float2*)(g_CG5 + ((size_t)b * XGC + 2 + o) * NP + gn) =
                    make_float2(h2.x / (1.f + expf(-v0)),
                                h2.y / (1.f + expf(-v1)));
            } else if (mode == 3) {
                *(float2*)(g_U + rowB + gn) =
                    make_float2(1.f / (1.f + expf(-v0)), 1.f / (1.f + expf(-v1)));
            } else { // mode 4
                float c0 = tanhf(v0), c1 = tanhf(v1);
                float2 u2 = *(const float2*)(g_U + rowB + gn);
                float2 h2 = *(const float2*)(g_H + rowB + gn);
                float hn0 = u2.x * h2.x + (1.f - u2.x) * c0;
                float hn1 = u2.y * h2.y + (1.f - u2.y) * c1;
                *(float2*)(g_H + rowB + gn) = make_float2(hn0, hn1);
                if (wr) {
                    *(float2*)(g_XG5 + ((size_t)b * XGC + 2 + o) * NP + gn) =
                        make_float2(hn0, hn1);
                    size_t rb = (((size_t)b * 128 + 64 + o) * NN + gn) * TT + (t + 1);
                    reps[rb] = hn0; reps[rb + TT] = hn1;
                    float wf = Wv[o];
                    p[2*q]   += wf * hn0;
                    p[2*q+1] += wf * hn1;
                }
            }
        }
    }

    if (mode == 1 || mode == 4) {
#pragma unroll
        for (int j = 0; j < 8; j++) sRed[(tx * 8 + j) * 17 + ty] = p[j];
        __syncthreads();
        if (tid < 128) {
            int gn = n0 + tid;
            if (gn < NN && (mode == 1 || wr)) {
                float s = bv[0];
#pragma unroll
                for (int yy = 0; yy < 16; yy++) s += sRed[tid * 17 + yy];
                if (mode == 1) {
                    size_t xi = ((size_t)b * NN + gn) * TT + t;
                    imp[xi] = s;
                    int mk = mask[xi];
                    float* xg0 = g_XG5 + (size_t)b * XGC * NP + gn;
                    float x2 = mk ? *xg0 : s;
                    *xg0 = x2;
                    float mf = xg0[NP];
                    float* cg0 = g_CG5 + (size_t)b * XGC * NP + gn;
                    cg0[0] = x2;
                    cg0[NP] = mf;
                } else {
                    size_t xi = ((size_t)b * NN + gn) * TT + (t + 1);
                    pred[xi] = s;
                    int mk = mask[xi];
                    float* xg0 = g_XG5 + (size_t)b * XGC * NP + gn;
                    xg0[0]  = mk ? x[xi] : s;
                    xg0[NP] = (float)mk;
                }
            }
        }
    }
    __syncthreads();
}

// ============================================================================
__global__ void __launch_bounds__(256, 2) kmain(
    const float* __restrict__ x, const float* __restrict__ af,
    const float* __restrict__ ab, const int* __restrict__ mask,
    const float* __restrict__ Wr,  const float* __restrict__ br,
    const float* __restrict__ Wu,  const float* __restrict__ bu,
    const float* __restrict__ Wc,  const float* __restrict__ bc,
    const float* __restrict__ Wfs, const float* __restrict__ bfs,
    const float* __restrict__ Wli, const float* __restrict__ bli,
    const float* __restrict__ Wgc, const float* __restrict__ bgc,
    const float* __restrict__ Wlo, const float* __restrict__ blo,
    const float* __restrict__ Wro, const float* __restrict__ bro,
    const float* __restrict__ pa,
    float* __restrict__ imp, float* __restrict__ pred, float* __restrict__ reps)
{
    __shared__ __align__(16) float sA[2 * KT * 128];
    __shared__ __align__(16) float sB[2 * KT * 128];
    __shared__ __align__(16) float sRed[128 * 17];

    const int tid = threadIdx.x;
    const int nb = gridDim.x;
    const int bid = blockIdx.x;
    const int gtid = bid * 256 + tid;
    const int gstr = nb * 256;
    const float pav = *pa;

    // ---- prologue ----
    for (int i = gtid; i < BB * 64 * NP; i += gstr) g_H[i] = 0.f;
    for (int i = gtid; i < 64 * 192; i += gstr) {
        int o = i / 192, k = i - o * 192;
        float s;
        if (k < 128) {
            s = 0.f;
            for (int j = 0; j < 64; j++) s += Wlo[o * 128 + j] * Wgc[j * 128 + k];
        } else s = Wlo[o * 128 + 64 + (k - 128)];
        g_Wc2[i] = s;
    }
    for (int i = gtid; i < 64; i += gstr) {
        float s = blo[i];
        for (int j = 0; j < 64; j++) s += Wlo[i * 128 + j] * bgc[j];
        g_bc2[i] = s;
    }
    // stage A for t=0 (h = 0)
    for (int i = gtid; i < BB * NN; i += gstr) {
        int b = i / NN, n = i - b * NN;
        size_t xi = ((size_t)b * NN + n) * TT;
        float s = bfs[0];
        pred[xi] = s;
        int mk = mask[xi];
        float* xg0 = g_XG5 + (size_t)b * XGC * NP + n;
        xg0[0]  = mk ? x[xi] : s;
        xg0[NP] = (float)mk;
    }
    for (int i = gtid; i < BB * 64 * NN; i += gstr) {
        int b = i / (64 * NN), r = i - b * (64 * NN);
        int c = r / NN, n = r - c * NN;
        g_XG5[((size_t)b * XGC + 2 + c) * NP + n] = 0.f;
        reps[(((size_t)b * 128 + 64 + c) * NN + n) * TT] = 0.f;
    }
    // A^2 for both supports
    for (int tile = bid; tile < 64; tile += nb) {
        int z = tile >> 5, rem = tile & 31;
        a2_tile(z ? ab : af, z ? g_A2b : g_A2f,
                (rem >> 3) * 128, (rem & 7) * 64, sA, sB);
    }
    gridbar();

    for (int t = 0; t < TT; t++) {
        // S1: conv li -> XIN
        for (int tile = bid; tile < 64; tile += nb)
            conv_tile(g_XG5, 1000, (size_t)XGC * NP, g_XG5, 0, Wli, bli, 66,
                      tile >> 2, (tile & 3) * 128, 0, t, pav, g_XIN,
                      Wro, bro, x, mask, imp, pred, reps, sA, sB, sRed);
        gridbar();

        // S2: diffusion XIN -> XIN2 (order-1, both supports)
        for (int tile = bid; tile < 128; tile += nb) {
            int z = tile >> 6, rem = tile & 63;
            diff_tile(g_XIN, g_XIN2, z ? ab : af, NN, 64, 0, z * 64,
                      (size_t)64 * NP, (size_t)128 * NP,
                      (rem >> 3) * 128, (rem & 7) * 64, sA, sB);
        }
        gridbar();

        // S3: gc∘lo conv (K=192) + fused stage-B
        for (int tile = bid; tile < 64; tile += nb)
            conv_tile(g_XIN2, 128, (size_t)128 * NP, g_H, (size_t)64 * NP,
                      g_Wc2, g_bc2, 192,
                      tile >> 2, (tile & 3) * 128, 1, t, pav, 0,
                      Wro, bro, x, mask, imp, pred, reps, sA, sB, sRed);
        gridbar();

        // S4: XG diffusion, both hops via A and A^2 (one stage)
        for (int tile = bid; tile < 288; tile += nb) {
            int hop = tile / 144, rem = tile - hop * 144;
            int z = rem / 72, r2 = rem - z * 72;
            const float* Am = hop ? (z ? g_A2b : g_A2f) : (z ? ab : af);
            diff_tile(g_XG5, g_XG5, Am, hop ? 512 : NN, 66, 0,
                      66 + z * 132 + hop * 66,
                      (size_t)XGC * NP, (size_t)XGC * NP,
                      (r2 >> 3) * 128, (r2 & 7) * 64, sA, sB);
        }
        gridbar();

        // S5: convs r (mode 2) and u (mode 3)
        for (int tile = bid; tile < 128; tile += nb) {
            int md = tile < 64 ? 2 : 3, tl = tile & 63;
            conv_tile(g_XG5, 1000, (size_t)XGC * NP, g_XG5, 0,
                      md == 2 ? Wr : Wu, md == 2 ? br : bu, 330,
                      tl >> 2, (tl & 3) * 128, md, t, pav, 0,
                      Wro, bro, x, mask, imp, pred, reps, sA, sB, sRed);
        }
        gridbar();

        // S6: CG diffusion, both hops
        for (int tile = bid; tile < 288; tile += nb) {
            int hop = tile / 144, rem = tile - hop * 144;
            int z = rem / 72, r2 = rem - z * 72;
            const float* Am = hop ? (z ? g_A2b : g_A2f) : (z ? ab : af);
            diff_tile(g_CG5, g_CG5, Am, hop ? 512 : NN, 66, 0,
                      66 + z * 132 + hop * 66,
                      (size_t)XGC * NP, (size_t)XGC * NP,
                      (r2 >> 3) * 128, (r2 & 7) * 64, sA, sB);
        }
        gridbar();

        // S7: conv c (mode 4) + h-update + fused stage-A(t+1)
        for (int tile = bid; tile < 64; tile += nb)
            conv_tile(g_CG5, 1000, (size_t)XGC * NP, g_CG5, 0, Wc, bc, 330,
                      tile >> 2, (tile & 3) * 128, 4, t, pav, 0,
                      Wfs, bfs, x, mask, imp, pred, reps, sA, sB, sRed);
        gridbar();
    }
}

extern "C" void kernel_launch(void* const* d_in, const int* in_sizes, int n_in,
                              void* d_out, int out_size)
{
    const float* x    = (const float*)d_in[0];
    const float* af   = (const float*)d_in[1];
    const float* ab   = (const float*)d_in[2];
    const int*   mask = (const int*)  d_in[3];
    const float* Wr   = (const float*)d_in[4];
    const float* br   = (const float*)d_in[5];
    const float* Wu   = (const float*)d_in[6];
    const float* bu   = (const float*)d_in[7];
    const float* Wc   = (const float*)d_in[8];
    const float* bc   = (const float*)d_in[9];
    const float* Wfs  = (const float*)d_in[10];
    const float* bfs  = (const float*)d_in[11];
    const float* Wli  = (const float*)d_in[12];
    const float* bli  = (const float*)d_in[13];
    const float* Wgc  = (const float*)d_in[14];
    const float* bgc  = (const float*)d_in[15];
    const float* Wlo  = (const float*)d_in[16];
    const float* blo  = (const float*)d_in[17];
    const float* Wro  = (const float*)d_in[18];
    const float* bro  = (const float*)d_in[19];
    const float* pa   = (const float*)d_in[20];

    float* out_imp  = (float*)d_out;
    float* out_pred = out_imp + (size_t)BB * NN * TT;
    float* out_reps = out_imp + (size_t)2 * BB * NN * TT;

    int dev = 0; cudaGetDevice(&dev);
    int sm = 0;
    cudaDeviceGetAttribute(&sm, cudaDevAttrMultiProcessorCount, dev);
    if (sm <= 0) sm = 148;
    int per = 0;
    cudaOccupancyMaxActiveBlocksPerMultiprocessor(&per, kmain, 256, 0);
    if (per < 1) per = 1;
    if (per > 2) per = 2;
    int nb = sm * per;

    kmain<<<nb, 256>>>(x, af, ab, mask, Wr, br, Wu, bu, Wc, bc,
                       Wfs, bfs, Wli, bli, Wgc, bgc, Wlo, blo, Wro, bro, pa,
                       out_imp, out_pred, out_reps);
}